// round 1
// baseline (speedup 1.0000x reference)
#include <cuda_runtime.h>

// Shapes (fixed for this problem)
#define Bb 8
#define Nn 1024
#define BN 8192          // B*N points
#define Fdim 128         // feature dim
#define Hh 4
#define Kk 32
#define HK 128           // H*K keys
#define FOUT 128
#define TP 64            // points per block in distance kernel

// smem strides (floats) chosen for bank-conflict control
#define KS 132           // keysT row stride: 4-aligned for LDS.128 reads
#define XS 65            // xT row stride: odd -> conflict-free scalar transpose writes
#define TSs 129          // tS row stride: odd -> conflict-free per-point row reads

#define OUT_ELEMS (Bb*Kk*FOUT)      // 32768
#define S_ELEMS   (BN*Kk)           // 262144

// Scratch (no allocation allowed -> device globals)
__device__ float g_pooled[Bb*Kk*FOUT];   // [b*32+k][128]
__device__ float g_linT[Fdim*FOUT];      // lin_w transposed: [f][fo]

// ---------------------------------------------------------------------------
// Kernel A: L1 distance (via min-sum identity) + student-t + per-head
// normalize + head-conv + softmax over K. Writes S directly.
// Grid: 128 blocks (64 points each), 256 threads, ~132KB dynamic smem.
// ---------------------------------------------------------------------------
__global__ __launch_bounds__(256, 1) void distS_kernel(
    const float* __restrict__ x, const float* __restrict__ keys,
    const float* __restrict__ convw, float* __restrict__ Sg)
{
    extern __shared__ float sm[];
    float* keysT = sm;                    // [128][KS]
    float* xT    = keysT + Fdim * KS;     // [128][XS]
    float* tS    = xT + Fdim * XS;        // [TP][TSs]
    float* ksum  = tS + TP * TSs;         // [128]
    float* xsum  = ksum + HK;             // [64]

    const int tid = threadIdx.x;
    const int p0  = blockIdx.x * TP;

    // Load keys (float4 coalesced) -> transposed smem [f][k]
    {
        const float4* k4 = (const float4*)keys;
        #pragma unroll
        for (int i4 = tid; i4 < HK * Fdim / 4; i4 += 256) {
            int k  = i4 >> 5;       // 32 float4 per 128-float row
            int f4 = i4 & 31;
            float4 v = k4[i4];
            keysT[(f4 * 4 + 0) * KS + k] = v.x;
            keysT[(f4 * 4 + 1) * KS + k] = v.y;
            keysT[(f4 * 4 + 2) * KS + k] = v.z;
            keysT[(f4 * 4 + 3) * KS + k] = v.w;
        }
    }
    // Load x tile (scalar coalesced) -> transposed smem [f][p]
    {
        #pragma unroll
        for (int idx = tid; idx < TP * Fdim; idx += 256) {
            int p = idx >> 7;
            int f = idx & 127;
            xT[f * XS + p] = x[(size_t)(p0 + p) * Fdim + f];
        }
    }
    __syncthreads();

    // Row sums: d(k,p) = ksum[k] + xsum[p] - 2*sum_f min(key,x)
    if (tid < HK) {
        float s = 0.f;
        #pragma unroll 8
        for (int f = 0; f < Fdim; f++) s += keysT[f * KS + tid];
        ksum[tid] = s;
    } else if (tid < HK + TP) {
        int p = tid - HK;
        float s = 0.f;
        #pragma unroll 8
        for (int f = 0; f < Fdim; f++) s += xT[f * XS + p];
        xsum[p] = s;
    }
    __syncthreads();

    // Register-tiled min-sum: each thread does 8 keys x 4 points
    const int kg = tid & 15;    // key group: keys [kg*8, kg*8+8)
    const int pg = tid >> 4;    // point group: points [pg*4, pg*4+4)
    const float* kp = keysT + kg * 8;
    const float* xp = xT + pg * 4;

    float acc[8][4];
    #pragma unroll
    for (int i = 0; i < 8; i++)
        #pragma unroll
        for (int j = 0; j < 4; j++) acc[i][j] = 0.f;

    #pragma unroll 4
    for (int f = 0; f < Fdim; f++) {
        float4 ka = *(const float4*)(kp + f * KS);
        float4 kb = *(const float4*)(kp + f * KS + 4);
        float kf[8] = {ka.x, ka.y, ka.z, ka.w, kb.x, kb.y, kb.z, kb.w};
        float xf[4];
        xf[0] = xp[f * XS + 0];
        xf[1] = xp[f * XS + 1];
        xf[2] = xp[f * XS + 2];
        xf[3] = xp[f * XS + 3];
        #pragma unroll
        for (int i = 0; i < 8; i++)
            #pragma unroll
            for (int j = 0; j < 4; j++)
                acc[i][j] += fminf(kf[i], xf[j]);   // FMNMX(alu) + FADD(fma)
    }

    // Student-t: t = 1/(1+d^2)  (TAU=1)
    #pragma unroll
    for (int i = 0; i < 8; i++) {
        #pragma unroll
        for (int j = 0; j < 4; j++) {
            int k = kg * 8 + i;
            int p = pg * 4 + j;
            float d = ksum[k] + xsum[p] - 2.f * acc[i][j];
            tS[p * TSs + k] = __fdividef(1.f, 1.f + d * d);
        }
    }
    __syncthreads();

    // Per-point: normalize per head, conv over heads, softmax over K
    if (tid < TP) {
        int p = tid;
        float C[Kk];
        #pragma unroll
        for (int k = 0; k < Kk; k++) C[k] = 0.f;
        #pragma unroll
        for (int h = 0; h < Hh; h++) {
            float tv[Kk];
            float hs = 0.f;
            #pragma unroll
            for (int k = 0; k < Kk; k++) {
                tv[k] = tS[p * TSs + h * Kk + k];
                hs += tv[k];
            }
            float w = __fdividef(convw[h], hs);
            #pragma unroll
            for (int k = 0; k < Kk; k++) C[k] += tv[k] * w;
        }
        float m = C[0];
        #pragma unroll
        for (int k = 1; k < Kk; k++) m = fmaxf(m, C[k]);
        float s = 0.f;
        #pragma unroll
        for (int k = 0; k < Kk; k++) { C[k] = __expf(C[k] - m); s += C[k]; }
        float inv = __fdividef(1.f, s);
        #pragma unroll
        for (int k = 0; k < Kk; k++) tS[p * TSs + k] = C[k] * inv;
    }
    __syncthreads();

    // Coalesced S write: [gn][k]
    #pragma unroll
    for (int e = tid; e < TP * Kk; e += 256) {
        int p = e >> 5;
        int k = e & 31;
        Sg[(size_t)p0 * Kk + e] = tS[p * TSs + k];
    }
}

// ---------------------------------------------------------------------------
// Kernel B: zero pooled scratch + transpose lin_w
// ---------------------------------------------------------------------------
__global__ void prep_kernel(const float* __restrict__ linw)
{
    int gid = blockIdx.x * blockDim.x + threadIdx.x;
    if (gid < OUT_ELEMS) g_pooled[gid] = 0.f;
    if (gid < Fdim * FOUT) {
        int fo = gid >> 7;
        int f  = gid & 127;
        g_linT[f * FOUT + fo] = linw[gid];
    }
}

// ---------------------------------------------------------------------------
// Kernel C: pooled[b][k][f] += sum_n S[b,n,k] * x[b,n,f]  (split over N,
// atomic accumulate). Grid (8 nchunks, 8 b), 256 threads, 4x4 reg tile.
// ---------------------------------------------------------------------------
__global__ __launch_bounds__(256) void pool_kernel(
    const float* __restrict__ x, const float* __restrict__ Sg)
{
    const int b  = blockIdx.y;
    const int n0 = blockIdx.x * 128;
    const int tid = threadIdx.x;
    const int kg = tid >> 5;     // k = kg*4..+3  (warp-uniform -> S broadcast)
    const int fg = tid & 31;     // f = fg*4..+3  (coalesced x)

    float acc[4][4];
    #pragma unroll
    for (int i = 0; i < 4; i++)
        #pragma unroll
        for (int j = 0; j < 4; j++) acc[i][j] = 0.f;

    #pragma unroll 4
    for (int n = 0; n < 128; n++) {
        int gn = b * Nn + n0 + n;
        float4 s4 = *(const float4*)(Sg + (size_t)gn * Kk + kg * 4);
        float4 x4 = *(const float4*)(x + (size_t)gn * Fdim + fg * 4);
        float sv[4] = {s4.x, s4.y, s4.z, s4.w};
        float xv[4] = {x4.x, x4.y, x4.z, x4.w};
        #pragma unroll
        for (int i = 0; i < 4; i++)
            #pragma unroll
            for (int j = 0; j < 4; j++)
                acc[i][j] += sv[i] * xv[j];
    }
    #pragma unroll
    for (int i = 0; i < 4; i++)
        #pragma unroll
        for (int j = 0; j < 4; j++)
            atomicAdd(&g_pooled[(b * Kk + kg * 4 + i) * Fdim + fg * 4 + j],
                      acc[i][j]);
}

// ---------------------------------------------------------------------------
// Kernel D: out[row][fo] = leaky( sum_f pooled[row][f] * lin_w[fo][f] )
// 64 blocks x 128 threads, 4 rows per block (reuses lin_wT read 4x).
// ---------------------------------------------------------------------------
__global__ __launch_bounds__(128) void out_kernel(float* __restrict__ out)
{
    const int r0 = blockIdx.x * 4;    // rows are (b*32 + k)
    const int tid = threadIdx.x;      // fo
    __shared__ float pr[4][Fdim];
    #pragma unroll
    for (int r = 0; r < 4; r++)
        pr[r][tid] = g_pooled[(r0 + r) * Fdim + tid];
    __syncthreads();

    float acc[4] = {0.f, 0.f, 0.f, 0.f};
    #pragma unroll 4
    for (int f = 0; f < Fdim; f++) {
        float w = g_linT[f * FOUT + tid];   // coalesced, L1-resident
        #pragma unroll
        for (int r = 0; r < 4; r++) acc[r] += pr[r][f] * w;
    }
    #pragma unroll
    for (int r = 0; r < 4; r++) {
        float v = acc[r];
        out[(r0 + r) * FOUT + tid] = (v >= 0.f) ? v : 0.01f * v;
    }
}

// ---------------------------------------------------------------------------
extern "C" void kernel_launch(void* const* d_in, const int* in_sizes, int n_in,
                              void* d_out, int out_size)
{
    const float* x     = (const float*)d_in[0];   // [8,1024,128]
    const float* keys  = (const float*)d_in[1];   // [4,32,128]
    const float* convw = (const float*)d_in[2];   // [4]
    const float* linw  = (const float*)d_in[3];   // [128,128]
    float* out = (float*)d_out;                   // [8,32,128]
    float* Sg  = out + OUT_ELEMS;                 // [8192,32]

    const int smemA = (Fdim * KS + Fdim * XS + TP * TSs + HK + TP) * (int)sizeof(float);
    cudaFuncSetAttribute(distS_kernel,
                         cudaFuncAttributeMaxDynamicSharedMemorySize, smemA);

    distS_kernel<<<BN / TP, 256, smemA>>>(x, keys, convw, Sg);
    prep_kernel<<<128, 256>>>(linw);
    pool_kernel<<<dim3(8, 8), 256>>>(x, Sg);
    out_kernel<<<64, 128>>>(out);
}

// round 2
// speedup vs baseline: 1.5564x; 1.5564x over previous
#include <cuda_runtime.h>

// Shapes (fixed for this problem)
#define Bb 8
#define Nn 1024
#define BN 8192          // B*N points
#define Fdim 128         // feature dim
#define Hh 4
#define Kk 32
#define HK 128           // H*K keys
#define FOUT 128
#define TP 64            // points per block in distance kernel
#define NCHUNK 16        // N-split for pooling partials

// smem strides (floats): 4-aligned for float4 LDS/STS, offset to spread banks
#define KS 132           // keysT row stride
#define XS 68            // xT row stride
#define TSs 132          // tS row stride

#define OUT_ELEMS (Bb*Kk*FOUT)      // 32768
#define S_ELEMS   (BN*Kk)           // 262144

// Scratch (no allocation allowed -> device globals)
__device__ float g_part[NCHUNK * Bb * Kk * FOUT];  // [c][b*32+k][128]
__device__ float g_linT[Fdim * FOUT];              // lin_w transposed: [f][fo]

// ---------------------------------------------------------------------------
// Kernel A: L1 distance (min-sum identity) + student-t + per-head normalize
// + head-conv + softmax over K. Writes S directly.
// Grid: 128 blocks (64 points each), 512 threads, ~137KB dynamic smem.
// ---------------------------------------------------------------------------
__global__ __launch_bounds__(512, 1) void distS_kernel(
    const float* __restrict__ x, const float* __restrict__ keys,
    const float* __restrict__ convw, float* __restrict__ Sg)
{
    extern __shared__ float sm[];
    float* keysT = sm;                    // [128][KS]
    float* xT    = keysT + Fdim * KS;     // [128][XS]
    float* tS    = xT + Fdim * XS;        // [TP][TSs]
    float* ksum  = tS + TP * TSs;         // [128]
    float* xsum  = ksum + HK;             // [64]

    const int tid = threadIdx.x;
    const int p0  = blockIdx.x * TP;

    // Load keys (float4 coalesced) -> transposed smem [f][k]
    {
        const float4* k4 = (const float4*)keys;
        #pragma unroll
        for (int i4 = tid; i4 < HK * Fdim / 4; i4 += 512) {
            int k  = i4 >> 5;       // 32 float4 per 128-float row
            int f4 = i4 & 31;
            float4 v = k4[i4];
            keysT[(f4 * 4 + 0) * KS + k] = v.x;
            keysT[(f4 * 4 + 1) * KS + k] = v.y;
            keysT[(f4 * 4 + 2) * KS + k] = v.z;
            keysT[(f4 * 4 + 3) * KS + k] = v.w;
        }
    }
    // Load x tile (coalesced) -> transposed smem [f][p]
    {
        #pragma unroll
        for (int idx = tid; idx < TP * Fdim; idx += 512) {
            int p = idx >> 7;
            int f = idx & 127;
            xT[f * XS + p] = x[(size_t)(p0 + p) * Fdim + f];
        }
    }
    __syncthreads();

    // Row sums: d(k,p) = ksum[k] + xsum[p] - 2*sum_f min(key,x)
    if (tid < HK) {
        float s = 0.f;
        #pragma unroll 8
        for (int f = 0; f < Fdim; f++) s += keysT[f * KS + tid];
        ksum[tid] = s;
    } else if (tid < HK + TP) {
        int p = tid - HK;
        float s = 0.f;
        #pragma unroll 8
        for (int f = 0; f < Fdim; f++) s += xT[f * XS + p];
        xsum[p] = s;
    }
    __syncthreads();

    // Register-tiled min-sum: each thread does 4 keys x 4 points.
    // kg spans the warp -> key LDS.128 conflict-free; pg warp-uniform ->
    // x LDS.128 is a broadcast.
    const int kg = tid & 31;    // keys  [kg*4, kg*4+4)
    const int pg = tid >> 5;    // points[pg*4, pg*4+4)
    const float* kp = keysT + kg * 4;
    const float* xp = xT + pg * 4;

    float acc[4][4];
    #pragma unroll
    for (int i = 0; i < 4; i++)
        #pragma unroll
        for (int j = 0; j < 4; j++) acc[i][j] = 0.f;

    #pragma unroll 4
    for (int f = 0; f < Fdim; f++) {
        float4 kv = *(const float4*)(kp + f * KS);
        float4 xv = *(const float4*)(xp + f * XS);
        float kf[4] = {kv.x, kv.y, kv.z, kv.w};
        float xf[4] = {xv.x, xv.y, xv.z, xv.w};
        #pragma unroll
        for (int i = 0; i < 4; i++)
            #pragma unroll
            for (int j = 0; j < 4; j++)
                acc[i][j] += fminf(kf[i], xf[j]);   // FMNMX(alu) + FADD(fma)
    }

    // Student-t: t = 1/(1+d^2)  (TAU=1); vector store rows of tS
    #pragma unroll
    for (int j = 0; j < 4; j++) {
        int p = pg * 4 + j;
        float4 tv;
        float d0 = ksum[kg * 4 + 0] + xsum[p] - 2.f * acc[0][j];
        float d1 = ksum[kg * 4 + 1] + xsum[p] - 2.f * acc[1][j];
        float d2 = ksum[kg * 4 + 2] + xsum[p] - 2.f * acc[2][j];
        float d3 = ksum[kg * 4 + 3] + xsum[p] - 2.f * acc[3][j];
        tv.x = __fdividef(1.f, 1.f + d0 * d0);
        tv.y = __fdividef(1.f, 1.f + d1 * d1);
        tv.z = __fdividef(1.f, 1.f + d2 * d2);
        tv.w = __fdividef(1.f, 1.f + d3 * d3);
        *(float4*)(tS + p * TSs + kg * 4) = tv;
    }
    __syncthreads();

    // Per-point: normalize per head, conv over heads, softmax over K
    if (tid < TP) {
        int p = tid;
        float C[Kk];
        #pragma unroll
        for (int k = 0; k < Kk; k++) C[k] = 0.f;
        #pragma unroll
        for (int h = 0; h < Hh; h++) {
            float tv[Kk];
            float hs = 0.f;
            #pragma unroll
            for (int k = 0; k < Kk; k++) {
                tv[k] = tS[p * TSs + h * Kk + k];
                hs += tv[k];
            }
            float w = __fdividef(convw[h], hs);
            #pragma unroll
            for (int k = 0; k < Kk; k++) C[k] += tv[k] * w;
        }
        float m = C[0];
        #pragma unroll
        for (int k = 1; k < Kk; k++) m = fmaxf(m, C[k]);
        float s = 0.f;
        #pragma unroll
        for (int k = 0; k < Kk; k++) { C[k] = __expf(C[k] - m); s += C[k]; }
        float inv = __fdividef(1.f, s);
        #pragma unroll
        for (int k = 0; k < Kk; k++) tS[p * TSs + k] = C[k] * inv;
    }
    __syncthreads();

    // Coalesced S write: [gn][k]
    #pragma unroll
    for (int e = tid; e < TP * Kk; e += 512) {
        int p = e >> 5;
        int k = e & 31;
        Sg[(size_t)p0 * Kk + e] = tS[p * TSs + k];
    }
}

// ---------------------------------------------------------------------------
// Kernel B: partial pooling (no atomics):
//   g_part[c][b*32+k][f] = sum_{n in chunk c} S[b,n,k] * x[b,n,f]
// Grid (NCHUNK, 8), 256 threads, 4x4 reg tile. Blocks with c==0 also
// transpose lin_w into g_linT.
// ---------------------------------------------------------------------------
__global__ __launch_bounds__(256) void pool_kernel(
    const float* __restrict__ x, const float* __restrict__ Sg,
    const float* __restrict__ linw)
{
    const int c  = blockIdx.x;
    const int b  = blockIdx.y;
    const int n0 = c * (Nn / NCHUNK);
    const int tid = threadIdx.x;
    const int kg = tid >> 5;     // k = kg*4..+3  (warp-uniform -> S broadcast)
    const int fg = tid & 31;     // f = fg*4..+3  (coalesced x)

    // Fold lin_w transpose into the first chunk's blocks (8 blocks x 2K elems)
    if (c == 0) {
        #pragma unroll
        for (int e = tid; e < 16 * Fdim; e += 256) {
            int fo = b * 16 + (e >> 7);
            int f  = e & 127;
            g_linT[f * FOUT + fo] = linw[fo * Fdim + f];
        }
    }

    float acc[4][4];
    #pragma unroll
    for (int i = 0; i < 4; i++)
        #pragma unroll
        for (int j = 0; j < 4; j++) acc[i][j] = 0.f;

    #pragma unroll 4
    for (int n = 0; n < Nn / NCHUNK; n++) {
        int gn = b * Nn + n0 + n;
        float4 s4 = *(const float4*)(Sg + (size_t)gn * Kk + kg * 4);
        float4 x4 = *(const float4*)(x + (size_t)gn * Fdim + fg * 4);
        float sv[4] = {s4.x, s4.y, s4.z, s4.w};
        float xv[4] = {x4.x, x4.y, x4.z, x4.w};
        #pragma unroll
        for (int i = 0; i < 4; i++)
            #pragma unroll
            for (int j = 0; j < 4; j++)
                acc[i][j] += sv[i] * xv[j];
    }
    #pragma unroll
    for (int i = 0; i < 4; i++) {
        float4 v = make_float4(acc[i][0], acc[i][1], acc[i][2], acc[i][3]);
        *(float4*)&g_part[((size_t)c * Bb * Kk + b * Kk + kg * 4 + i) * Fdim
                          + fg * 4] = v;
    }
}

// ---------------------------------------------------------------------------
// Kernel C: reduce partials + linear + LeakyReLU.
// Grid 256 (one row = b*32+k each), 128 threads (fo). Fully unrolled
// independent loads -> high MLP, latency hidden.
// ---------------------------------------------------------------------------
__global__ __launch_bounds__(128) void out_kernel(float* __restrict__ out)
{
    const int row = blockIdx.x;
    const int tid = threadIdx.x;
    __shared__ float pr[Fdim];

    float s = 0.f;
    #pragma unroll
    for (int cc = 0; cc < NCHUNK; cc++)
        s += g_part[((size_t)cc * Bb * Kk + row) * Fdim + tid];
    pr[tid] = s;
    __syncthreads();

    float acc = 0.f;
    #pragma unroll
    for (int f = 0; f < Fdim; f++)
        acc += pr[f] * g_linT[f * FOUT + tid];   // coalesced, L2-resident

    out[(size_t)row * FOUT + tid] = (acc >= 0.f) ? acc : 0.01f * acc;
}

// ---------------------------------------------------------------------------
extern "C" void kernel_launch(void* const* d_in, const int* in_sizes, int n_in,
                              void* d_out, int out_size)
{
    const float* x     = (const float*)d_in[0];   // [8,1024,128]
    const float* keys  = (const float*)d_in[1];   // [4,32,128]
    const float* convw = (const float*)d_in[2];   // [4]
    const float* linw  = (const float*)d_in[3];   // [128,128]
    float* out = (float*)d_out;                   // [8,32,128]
    float* Sg  = out + OUT_ELEMS;                 // [8192,32]

    const int smemA = (Fdim * KS + Fdim * XS + TP * TSs + HK + TP)
                      * (int)sizeof(float);
    cudaFuncSetAttribute(distS_kernel,
                         cudaFuncAttributeMaxDynamicSharedMemorySize, smemA);

    distS_kernel<<<BN / TP, 512, smemA>>>(x, keys, convw, Sg);
    pool_kernel<<<dim3(NCHUNK, Bb), 256>>>(x, Sg, linw);
    out_kernel<<<Bb * Kk, 128>>>(out);
}